// round 15
// baseline (speedup 1.0000x reference)
#include <cuda_runtime.h>
#include <cuda_fp16.h>
#include <cstdint>

#define HW 65536
#define M_PER_CH (16*HW)

__device__ __half g_convh[(size_t)16*64*HW];   // 128 MB fp16 scratch
__device__ float g_psum[64*148];
__device__ float g_psq[64*148];
__device__ float g_scale[64];
__device__ float g_shift[64];

// SMEM layout (dynamic):
//   W : [0, 82944)            9 taps x [64 co][72 halves] (stride 144B)
//   A : [82944, +6*19008)     6-slot ring x [132 px][72 halves] (stride 144B)
#define WOFF 0
#define AOFF 82944
#define ATILE 19008
#define SMEM_REQ (82944 + 6*19008)
#define WTAP 9216      // 64*144

#define NCH 43         // iterations per 128-row chain (3 rows each, last=2)
#define NITER_TOT (64*NCH)

__device__ __forceinline__ uint32_t s2u(const void* p) {
    uint32_t a;
    asm("{ .reg .u64 t; cvta.to.shared.u64 t, %1; cvt.u32.u64 %0, t; }" : "=r"(a) : "l"(p));
    return a;
}
__device__ __forceinline__ void ldsm4(uint32_t& r0, uint32_t& r1, uint32_t& r2, uint32_t& r3,
                                      uint32_t addr) {
    asm volatile("ldmatrix.sync.aligned.m8n8.x4.shared.b16 {%0,%1,%2,%3}, [%4];"
                 : "=r"(r0), "=r"(r1), "=r"(r2), "=r"(r3) : "r"(addr));
}
__device__ __forceinline__ void mma16816(float* c, uint32_t a0, uint32_t a1, uint32_t a2,
                                         uint32_t a3, uint32_t b0, uint32_t b1) {
    asm volatile("mma.sync.aligned.m16n8k16.row.col.f32.f16.f16.f32 "
                 "{%0,%1,%2,%3}, {%4,%5,%6,%7}, {%8,%9}, {%0,%1,%2,%3};"
                 : "+f"(c[0]), "+f"(c[1]), "+f"(c[2]), "+f"(c[3])
                 : "r"(a0), "r"(a1), "r"(a2), "r"(a3), "r"(b0), "r"(b1));
}
__device__ __forceinline__ uint32_t packh2(float a, float b) {
    __half2 h = __floats2half2_rn(a, b);
    return *(uint32_t*)&h;
}
__device__ __forceinline__ int mod6(int v) {            // v >= 0, small
    int m = v % 6; return m;
}

// Prefetch one x row's worth for this thread (row-group rg owns one row).
// tg in [0,128): oct = tg&7 (fixed ci octet), px = (tg>>3) + 16*s, s=0..7.
// Edge (px 128..131): threads tg<32, px = 128 + (tg>>3), same oct.
__device__ __forceinline__ void stage_load3(const float* __restrict__ x, int n, int hrow,
                                            int w0, int tg, uint4 pk[8], uint4& pke)
{
    const bool rowok = ((unsigned)hrow < 256u);
    const int oct = tg & 7;
    const int pxb = tg >> 3;
    const size_t cibase = (((size_t)(n*64 + oct*8)) << 16);

    #pragma unroll
    for (int s = 0; s < 8; s++) {
        const int px = pxb + 16*s;
        const int wg = w0 - 2 + px;
        const bool wok = rowok && ((unsigned)wg < 256u);
        const size_t base = cibase + (size_t)(hrow*256 + wg);
        float v[8];
        #pragma unroll
        for (int i = 0; i < 8; i++)
            v[i] = wok ? __ldg(&x[base + ((size_t)i << 16)]) : 0.f;
        pk[s].x = packh2(v[0], v[1]);
        pk[s].y = packh2(v[2], v[3]);
        pk[s].z = packh2(v[4], v[5]);
        pk[s].w = packh2(v[6], v[7]);
    }
    pke = make_uint4(0, 0, 0, 0);
    if (tg < 32) {
        const int px = 128 + (tg >> 3);
        const int wg = w0 - 2 + px;
        const bool wok = rowok && ((unsigned)wg < 256u);
        const size_t base = cibase + (size_t)(hrow*256 + wg);
        float v[8];
        #pragma unroll
        for (int i = 0; i < 8; i++)
            v[i] = wok ? __ldg(&x[base + ((size_t)i << 16)]) : 0.f;
        pke.x = packh2(v[0], v[1]);
        pke.y = packh2(v[2], v[3]);
        pke.z = packh2(v[4], v[5]);
        pke.w = packh2(v[6], v[7]);
    }
}

__device__ __forceinline__ void stage_store3(char* sm, int slot, int tg,
                                             const uint4 pk[8], const uint4& pke)
{
    char* base = sm + AOFF + slot * ATILE;
    const int oct = tg & 7;
    const int pxb = tg >> 3;
    #pragma unroll
    for (int s = 0; s < 8; s++)
        *(uint4*)(base + (pxb + 16*s)*144 + oct*16) = pk[s];
    if (tg < 32)
        *(uint4*)(base + (128 + (tg >> 3))*144 + oct*16) = pke;
}

// ---------------------------------------------------------------------------
// HMMA implicit-GEMM dilated conv + fused channel stats.
// 384 threads / 12 warps: triple-row iterations; warp = (row, M-pos, N-half),
// each warp M=64 x N=32 (c[64]). 6-slot ring, 2 syncs/iter.
// ldsm traffic/output matches the best-known (R8) with 12 warps to hide it.
// ---------------------------------------------------------------------------
__global__ __launch_bounds__(384, 1)
void conv_tc(const float* __restrict__ x, const float* __restrict__ wgt)
{
    extern __shared__ char sm[];
    __shared__ float sredS[12*32], sredQ[12*32];

    const int t  = threadIdx.x;
    const int L  = t & 31;
    const int wi = t >> 5;
    const int rsel = wi >> 2;            // warp's row within triple (0..2)
    const int Mq   = (wi >> 1) & 1;      // 0: px 0..63, 1: px 64..127
    const int Nb   = (wi & 1) * 32;
    const int rg   = t >> 7;             // staging row group 0..2
    const int tg   = t & 127;

    // ---- stage weights: [tap][co][ci] fp16, row stride 144B ----
    {
        const int co = t & 63;
        const int o0 = (t >> 6) & 3;     // 0..3 over 384 threads -> 0..5; mask
        const int grp = t >> 6;          // 0..5
        if (grp < 4) {
            for (int r = 0; r < 2; r++) {
                const int oct = o0 + 4*r;
                for (int tap = 0; tap < 9; tap++) {
                    float v[8];
                    #pragma unroll
                    for (int i = 0; i < 8; i++)
                        v[i] = __ldg(&wgt[co*576 + (oct*8 + i)*9 + tap]);
                    uint4 p;
                    p.x = packh2(v[0], v[1]); p.y = packh2(v[2], v[3]);
                    p.z = packh2(v[4], v[5]); p.w = packh2(v[6], v[7]);
                    *(uint4*)(sm + WOFF + tap*WTAP + co*144 + oct*16) = p;
                }
            }
        }
    }

    const uint32_t Ab = s2u(sm + AOFF);
    const uint32_t Wb = s2u(sm + WOFF);

    uint32_t aoffm[4];
    #pragma unroll
    for (int mi = 0; mi < 4; mi++)
        aoffm[mi] = (uint32_t)((Mq*64 + mi*16 + (L & 15)) * 144 + ((L >> 4) * 16));
    const uint32_t bconst = Wb + (uint32_t)((Nb + ((L >> 3) & 3)*8 + (L & 7)) * 144);

    float2 accS2[4], accQ2[4];
    #pragma unroll
    for (int i = 0; i < 4; i++) {
        accS2[i] = make_float2(0.f, 0.f);
        accQ2[i] = make_float2(0.f, 0.f);
    }

    const int g0 = (blockIdx.x * NITER_TOT) / 148;
    const int g1 = ((blockIdx.x + 1) * NITER_TOT) / 148;

    uint4 pk[8], pke;
    int I = g0;

    __syncthreads();   // weights staged

    while (I < g1) {
        const int chain = I / NCH;
        const int i0 = I - chain*NCH;
        const int n  = chain >> 2;
        const int wc = (chain >> 1) & 1;
        const int p  = chain & 1;
        const int w0 = wc << 7;
        const int Iend = ((chain + 1)*NCH < g1) ? (chain + 1)*NCH : g1;
        int u0 = 3*i0;

        __syncthreads();   // prior chain's ldsm reads done before slot reuse

        // prologue: stage slots u0..u0+2 (x row for slot s is p+2s-2)
        stage_load3(x, n, p + 2*(u0 + rg) - 2, w0, tg, pk, pke);
        stage_store3(sm, mod6(u0 + rg), tg, pk, pke);
        // prefetch slots u0+3..u0+5
        stage_load3(x, n, p + 2*(u0 + 3 + rg) - 2, w0, tg, pk, pke);

        for (; I < Iend; I++, u0 += 3) {
            stage_store3(sm, mod6(u0 + 3 + rg), tg, pk, pke);
            __syncthreads();

            // prefetch next triple (hidden under MMAs)
            if (I + 1 < Iend)
                stage_load3(x, n, p + 2*(u0 + 6 + rg) - 2, w0, tg, pk, pke);

            const int u = u0 + rsel;           // this warp's output row index
            if (u < 128) {
                float c[64];
                #pragma unroll
                for (int i = 0; i < 64; i++) c[i] = 0.f;

                const int su = mod6(u);
                #pragma unroll
                for (int kh = 0; kh < 3; kh++) {
                    int sl = su + kh; if (sl >= 6) sl -= 6;
                    const uint32_t abase = Ab + (uint32_t)sl * ATILE;
                    #pragma unroll
                    for (int kw = 0; kw < 3; kw++) {
                        const uint32_t boffb = (uint32_t)((kh*3 + kw)*WTAP);
                        #pragma unroll
                        for (int ks = 0; ks < 4; ks++) {
                            const uint32_t aoff = (uint32_t)(kw*288 + ks*32);
                            const uint32_t boff = boffb + (uint32_t)(ks*32);
                            uint32_t A0[4], A1[4], A2[4], A3[4], B0[4], B1[4];
                            ldsm4(A0[0], A0[1], A0[2], A0[3], abase + aoffm[0] + aoff);
                            ldsm4(A1[0], A1[1], A1[2], A1[3], abase + aoffm[1] + aoff);
                            ldsm4(A2[0], A2[1], A2[2], A2[3], abase + aoffm[2] + aoff);
                            ldsm4(A3[0], A3[1], A3[2], A3[3], abase + aoffm[3] + aoff);
                            ldsm4(B0[0], B0[1], B0[2], B0[3], bconst + boff);
                            ldsm4(B1[0], B1[1], B1[2], B1[3], bconst + boff + 16);
                            #pragma unroll
                            for (int nj = 0; nj < 4; nj++) {
                                mma16816(&c[nj*4],      A0[0],A0[1],A0[2],A0[3], B0[nj], B1[nj]);
                                mma16816(&c[16+nj*4],   A1[0],A1[1],A1[2],A1[3], B0[nj], B1[nj]);
                                mma16816(&c[32+nj*4],   A2[0],A2[1],A2[2],A2[3], B0[nj], B1[nj]);
                                mma16816(&c[48+nj*4],   A3[0],A3[1],A3[2],A3[3], B0[nj], B1[nj]);
                            }
                        }
                    }
                }

                // ---- epilogue: frags -> g_convh (fp16) + stats in regs ----
                const int h_r = p + 2*u;
                const int coB = 2*(L & 3);
                const int pxq = L >> 2;
                #pragma unroll
                for (int nj = 0; nj < 4; nj++) {
                    const int co = Nb + nj*8 + coB;
                    const size_t gb0 = (((size_t)(n*64 + co)) << 16) + (size_t)h_r*256 + w0;
                    const size_t gb1 = gb0 + HW;   // co+1
                    #pragma unroll
                    for (int mi = 0; mi < 4; mi++) {
                        const float* cf = &c[mi*16 + nj*4];
                        const int px0 = Mq*64 + mi*16 + pxq;
                        g_convh[gb0 + px0]     = __float2half_rn(cf[0]);
                        g_convh[gb1 + px0]     = __float2half_rn(cf[1]);
                        g_convh[gb0 + px0 + 8] = __float2half_rn(cf[2]);
                        g_convh[gb1 + px0 + 8] = __float2half_rn(cf[3]);
                        accS2[nj].x += cf[0] + cf[2];
                        accS2[nj].y += cf[1] + cf[3];
                        accQ2[nj].x += cf[0]*cf[0] + cf[2]*cf[2];
                        accQ2[nj].y += cf[1]*cf[1] + cf[3]*cf[3];
                    }
                }
            }
            __syncthreads();   // all ldsm reads done before next stores
        }
    }

    // ---- stats: butterfly over lanes sharing (L&3), write own 32-co half ----
    #pragma unroll
    for (int nj = 0; nj < 4; nj++) {
        #pragma unroll
        for (int off = 4; off < 32; off <<= 1) {
            accS2[nj].x += __shfl_xor_sync(0xffffffffu, accS2[nj].x, off);
            accS2[nj].y += __shfl_xor_sync(0xffffffffu, accS2[nj].y, off);
            accQ2[nj].x += __shfl_xor_sync(0xffffffffu, accQ2[nj].x, off);
            accQ2[nj].y += __shfl_xor_sync(0xffffffffu, accQ2[nj].y, off);
        }
    }
    if (L < 4) {
        #pragma unroll
        for (int nj = 0; nj < 4; nj++) {
            const int lc = nj*8 + 2*L;
            sredS[wi*32 + lc]     = accS2[nj].x;
            sredS[wi*32 + lc + 1] = accS2[nj].y;
            sredQ[wi*32 + lc]     = accQ2[nj].x;
            sredQ[wi*32 + lc + 1] = accQ2[nj].y;
        }
    }
    __syncthreads();
    if (t < 64) {
        const int half = t >> 5;           // co<32 -> warps with (wi&1)==0
        const int lc = t & 31;
        float s = 0.f, q = 0.f;
        #pragma unroll
        for (int j = 0; j < 6; j++) {
            const int w = 2*j + half;
            s += sredS[w*32 + lc];
            q += sredQ[w*32 + lc];
        }
        g_psum[t*148 + blockIdx.x] = s;
        g_psq [t*148 + blockIdx.x] = q;
    }
}

// ---------------------------------------------------------------------------
__global__ void finalize_stats(const float* __restrict__ gamma,
                               const float* __restrict__ beta)
{
    int c = threadIdx.x;   // 64 threads
    float s = 0.f, q = 0.f;
    for (int b = 0; b < 148; b++) { s += g_psum[c*148 + b]; q += g_psq[c*148 + b]; }
    const float invM = 1.f / (float)M_PER_CH;
    float m   = s * invM;
    float var = q * invM - m*m;
    float inv = rsqrtf(var + 1e-5f);
    float sc  = gamma[c] * inv;
    g_scale[c] = sc;
    g_shift[c] = beta[c] - sc * m;
}

// ---------------------------------------------------------------------------
// normalize + ReLU + 4x4 block bitonic sort; write [a | y]  (DRAM roofline)
// ---------------------------------------------------------------------------
__global__ __launch_bounds__(256) void bn_sort_kernel(float* __restrict__ out)
{
    int tid = blockIdx.x * 256 + threadIdx.x;
    int bw = tid & 63, bh = (tid >> 6) & 63, c = (tid >> 12) & 63, n = tid >> 18;
    float sc = g_scale[c], sh = g_shift[c];

    size_t ibase = ((((size_t)(n*64 + c)) << 8) + bh*4) * 256 + bw*4;
    float v[16];
    #pragma unroll
    for (int r = 0; r < 4; r++) {
        uint2 raw = *(const uint2*)&g_convh[ibase + (size_t)r*256];
        float2 f01 = __half22float2(*(__half2*)&raw.x);
        float2 f23 = __half22float2(*(__half2*)&raw.y);
        v[r*4+0] = fmaxf(fmaf(f01.x, sc, sh), 0.f);
        v[r*4+1] = fmaxf(fmaf(f01.y, sc, sh), 0.f);
        v[r*4+2] = fmaxf(fmaf(f23.x, sc, sh), 0.f);
        v[r*4+3] = fmaxf(fmaf(f23.y, sc, sh), 0.f);
    }
    size_t obase = ((((size_t)(n*128 + c)) << 8) + bh*4) * 256 + bw*4;
    #pragma unroll
    for (int r = 0; r < 4; r++)
        *(float4*)&out[obase + (size_t)r*256] =
            make_float4(v[r*4+0], v[r*4+1], v[r*4+2], v[r*4+3]);

    #pragma unroll
    for (int k = 2; k <= 16; k <<= 1)
        #pragma unroll
        for (int j = k >> 1; j > 0; j >>= 1)
            #pragma unroll
            for (int i = 0; i < 16; i++) {
                int ix = i ^ j;
                if (ix > i) {
                    float a = v[i], b = v[ix];
                    float lo = fminf(a, b), hi = fmaxf(a, b);
                    bool up = ((i & k) == 0);
                    v[i] = up ? lo : hi; v[ix] = up ? hi : lo;
                }
            }

    size_t ybase = obase + ((size_t)64 << 16);
    #pragma unroll
    for (int r = 0; r < 4; r++)
        *(float4*)&out[ybase + (size_t)r*256] =
            make_float4(v[r*4+0], v[r*4+1], v[r*4+2], v[r*4+3]);
}

// ---------------------------------------------------------------------------
extern "C" void kernel_launch(void* const* d_in, const int* in_sizes, int n_in,
                              void* d_out, int out_size)
{
    const float* x     = (const float*)d_in[0];
    const float* wgt   = (const float*)d_in[1];
    // d_in[2] = conv_b : cancels exactly in training-mode BN
    const float* gamma = (const float*)d_in[3];
    const float* beta  = (const float*)d_in[4];
    float* out = (float*)d_out;

    cudaFuncSetAttribute(conv_tc, cudaFuncAttributeMaxDynamicSharedMemorySize, SMEM_REQ);
    conv_tc<<<148, 384, SMEM_REQ>>>(x, wgt);
    finalize_stats<<<1, 64>>>(gamma, beta);
    bn_sort_kernel<<<16384, 256>>>(out);
}

// round 16
// speedup vs baseline: 1.1849x; 1.1849x over previous
#include <cuda_runtime.h>
#include <cuda_fp16.h>
#include <cstdint>

#define HW 65536
#define M_PER_CH (16*HW)

__device__ __half g_convh[(size_t)16*64*HW];   // 128 MB fp16 scratch
__device__ float g_psum[64*148];
__device__ float g_psq[64*148];
__device__ float g_scale[64];
__device__ float g_shift[64];

// SMEM layout (dynamic):
//   W : [0, 82944)            9 taps x [64 co][72 halves] (stride 144B)
//   A : [82944, +6*19008)     6-slot ring x [132 px][72 halves] (stride 144B)
#define WOFF 0
#define AOFF 82944
#define ATILE 19008
#define SMEM_REQ (82944 + 6*19008)
#define WTAP 9216      // 64*144

#define NCH 43         // iterations per 128-row chain (3 rows each, last=2)
#define NITER_TOT (64*NCH)

__device__ __forceinline__ uint32_t s2u(const void* p) {
    uint32_t a;
    asm("{ .reg .u64 t; cvta.to.shared.u64 t, %1; cvt.u32.u64 %0, t; }" : "=r"(a) : "l"(p));
    return a;
}
__device__ __forceinline__ void ldsm4(uint32_t& r0, uint32_t& r1, uint32_t& r2, uint32_t& r3,
                                      uint32_t addr) {
    asm volatile("ldmatrix.sync.aligned.m8n8.x4.shared.b16 {%0,%1,%2,%3}, [%4];"
                 : "=r"(r0), "=r"(r1), "=r"(r2), "=r"(r3) : "r"(addr));
}
__device__ __forceinline__ void mma16816(float* c, uint32_t a0, uint32_t a1, uint32_t a2,
                                         uint32_t a3, uint32_t b0, uint32_t b1) {
    asm volatile("mma.sync.aligned.m16n8k16.row.col.f32.f16.f16.f32 "
                 "{%0,%1,%2,%3}, {%4,%5,%6,%7}, {%8,%9}, {%0,%1,%2,%3};"
                 : "+f"(c[0]), "+f"(c[1]), "+f"(c[2]), "+f"(c[3])
                 : "r"(a0), "r"(a1), "r"(a2), "r"(a3), "r"(b0), "r"(b1));
}
__device__ __forceinline__ uint32_t packh2(float a, float b) {
    __half2 h = __floats2half2_rn(a, b);
    return *(uint32_t*)&h;
}
__device__ __forceinline__ int mod6(int v) { return v % 6; }

// Coalesced: lane = pixel. tg in [0,128): px = tg; loop over 8 ci-octets.
// Edge px 128..131 handled by tg<32 (px = 128+(tg&3), oct = tg>>2).
__device__ __forceinline__ void stage_load3(const float* __restrict__ x, int n, int hrow,
                                            int w0, int tg, uint4 pk[8], uint4& pke)
{
    const bool rowok = ((unsigned)hrow < 256u);
    const int px = tg;                   // 0..127
    const int wg = w0 - 2 + px;
    const bool wok = rowok && ((unsigned)wg < 256u);
    const size_t rb = (size_t)(hrow*256 + wg);

    #pragma unroll
    for (int r = 0; r < 8; r++) {
        const size_t base = (((size_t)(n*64 + r*8)) << 16) + rb;
        float v[8];
        #pragma unroll
        for (int i = 0; i < 8; i++)
            v[i] = wok ? __ldg(&x[base + ((size_t)i << 16)]) : 0.f;
        pk[r].x = packh2(v[0], v[1]);
        pk[r].y = packh2(v[2], v[3]);
        pk[r].z = packh2(v[4], v[5]);
        pk[r].w = packh2(v[6], v[7]);
    }
    pke = make_uint4(0, 0, 0, 0);
    if (tg < 32) {
        const int pxe = 128 + (tg & 3);
        const int oct = tg >> 2;         // 0..7
        const int we = w0 - 2 + pxe;
        const bool ewok = rowok && ((unsigned)we < 256u);
        const size_t base = (((size_t)(n*64 + oct*8)) << 16) + (size_t)(hrow*256 + we);
        float v[8];
        #pragma unroll
        for (int i = 0; i < 8; i++)
            v[i] = ewok ? __ldg(&x[base + ((size_t)i << 16)]) : 0.f;
        pke.x = packh2(v[0], v[1]);
        pke.y = packh2(v[2], v[3]);
        pke.z = packh2(v[4], v[5]);
        pke.w = packh2(v[6], v[7]);
    }
}

__device__ __forceinline__ void stage_store3(char* sm, int slot, int tg,
                                             const uint4 pk[8], const uint4& pke)
{
    char* base = sm + AOFF + slot * ATILE;
    #pragma unroll
    for (int r = 0; r < 8; r++)
        *(uint4*)(base + tg*144 + r*16) = pk[r];
    if (tg < 32)
        *(uint4*)(base + (128 + (tg & 3))*144 + (tg >> 2)*16) = pke;
}

// ---------------------------------------------------------------------------
// HMMA implicit-GEMM dilated conv + fused channel stats.
// 384 threads / 12 warps: triple-row iterations; warp = (row, M-pos, N-half),
// each warp M=64 x N=32 (c[64]); B fragments amortized over M=64.
// 6-slot ring, 2 syncs/iter; COALESCED staging (lane = pixel).
// ---------------------------------------------------------------------------
__global__ __launch_bounds__(384, 1)
void conv_tc(const float* __restrict__ x, const float* __restrict__ wgt)
{
    extern __shared__ char sm[];
    __shared__ float sredS[12*32], sredQ[12*32];

    const int t  = threadIdx.x;
    const int L  = t & 31;
    const int wi = t >> 5;
    const int rsel = wi >> 2;            // warp's row within triple (0..2)
    const int Mq   = (wi >> 1) & 1;      // 0: px 0..63, 1: px 64..127
    const int Nb   = (wi & 1) * 32;
    const int rg   = t >> 7;             // staging row group 0..2
    const int tg   = t & 127;

    // ---- stage weights: [tap][co][ci] fp16, row stride 144B ----
    {
        const int co = t & 63;
        const int o0 = (t >> 6) & 3;
        const int grp = t >> 6;          // 0..5
        if (grp < 4) {
            for (int r = 0; r < 2; r++) {
                const int oct = o0 + 4*r;
                for (int tap = 0; tap < 9; tap++) {
                    float v[8];
                    #pragma unroll
                    for (int i = 0; i < 8; i++)
                        v[i] = __ldg(&wgt[co*576 + (oct*8 + i)*9 + tap]);
                    uint4 p;
                    p.x = packh2(v[0], v[1]); p.y = packh2(v[2], v[3]);
                    p.z = packh2(v[4], v[5]); p.w = packh2(v[6], v[7]);
                    *(uint4*)(sm + WOFF + tap*WTAP + co*144 + oct*16) = p;
                }
            }
        }
    }

    const uint32_t Ab = s2u(sm + AOFF);
    const uint32_t Wb = s2u(sm + WOFF);

    uint32_t aoffm[4];
    #pragma unroll
    for (int mi = 0; mi < 4; mi++)
        aoffm[mi] = (uint32_t)((Mq*64 + mi*16 + (L & 15)) * 144 + ((L >> 4) * 16));
    const uint32_t bconst = Wb + (uint32_t)((Nb + ((L >> 3) & 3)*8 + (L & 7)) * 144);

    float2 accS2[4], accQ2[4];
    #pragma unroll
    for (int i = 0; i < 4; i++) {
        accS2[i] = make_float2(0.f, 0.f);
        accQ2[i] = make_float2(0.f, 0.f);
    }

    const int g0 = (blockIdx.x * NITER_TOT) / 148;
    const int g1 = ((blockIdx.x + 1) * NITER_TOT) / 148;

    uint4 pk[8], pke;
    int I = g0;

    __syncthreads();   // weights staged

    while (I < g1) {
        const int chain = I / NCH;
        const int i0 = I - chain*NCH;
        const int n  = chain >> 2;
        const int wc = (chain >> 1) & 1;
        const int p  = chain & 1;
        const int w0 = wc << 7;
        const int Iend = ((chain + 1)*NCH < g1) ? (chain + 1)*NCH : g1;
        int u0 = 3*i0;

        __syncthreads();   // prior chain's ldsm reads done before slot reuse

        // prologue: stage slots u0..u0+2 (slot s holds x row p+2s-2)
        stage_load3(x, n, p + 2*(u0 + rg) - 2, w0, tg, pk, pke);
        stage_store3(sm, mod6(u0 + rg), tg, pk, pke);
        stage_load3(x, n, p + 2*(u0 + 3 + rg) - 2, w0, tg, pk, pke);

        for (; I < Iend; I++, u0 += 3) {
            stage_store3(sm, mod6(u0 + 3 + rg), tg, pk, pke);
            __syncthreads();

            // prefetch next triple (hidden under MMAs)
            if (I + 1 < Iend)
                stage_load3(x, n, p + 2*(u0 + 6 + rg) - 2, w0, tg, pk, pke);

            const int u = u0 + rsel;           // this warp's output row index
            if (u < 128) {
                float c[64];
                #pragma unroll
                for (int i = 0; i < 64; i++) c[i] = 0.f;

                const int su = mod6(u);
                #pragma unroll
                for (int kh = 0; kh < 3; kh++) {
                    int sl = su + kh; if (sl >= 6) sl -= 6;
                    const uint32_t abase = Ab + (uint32_t)sl * ATILE;
                    #pragma unroll
                    for (int kw = 0; kw < 3; kw++) {
                        const uint32_t boffb = (uint32_t)((kh*3 + kw)*WTAP);
                        #pragma unroll
                        for (int ks = 0; ks < 4; ks++) {
                            const uint32_t aoff = (uint32_t)(kw*288 + ks*32);
                            const uint32_t boff = boffb + (uint32_t)(ks*32);
                            uint32_t A0[4], A1[4], A2[4], A3[4], B0[4], B1[4];
                            ldsm4(A0[0], A0[1], A0[2], A0[3], abase + aoffm[0] + aoff);
                            ldsm4(A1[0], A1[1], A1[2], A1[3], abase + aoffm[1] + aoff);
                            ldsm4(A2[0], A2[1], A2[2], A2[3], abase + aoffm[2] + aoff);
                            ldsm4(A3[0], A3[1], A3[2], A3[3], abase + aoffm[3] + aoff);
                            ldsm4(B0[0], B0[1], B0[2], B0[3], bconst + boff);
                            ldsm4(B1[0], B1[1], B1[2], B1[3], bconst + boff + 16);
                            #pragma unroll
                            for (int nj = 0; nj < 4; nj++) {
                                mma16816(&c[nj*4],    A0[0],A0[1],A0[2],A0[3], B0[nj], B1[nj]);
                                mma16816(&c[16+nj*4], A1[0],A1[1],A1[2],A1[3], B0[nj], B1[nj]);
                                mma16816(&c[32+nj*4], A2[0],A2[1],A2[2],A2[3], B0[nj], B1[nj]);
                                mma16816(&c[48+nj*4], A3[0],A3[1],A3[2],A3[3], B0[nj], B1[nj]);
                            }
                        }
                    }
                }

                // ---- epilogue: frags -> g_convh (fp16) + stats in regs ----
                const int h_r = p + 2*u;
                const int coB = 2*(L & 3);
                const int pxq = L >> 2;
                #pragma unroll
                for (int nj = 0; nj < 4; nj++) {
                    const int co = Nb + nj*8 + coB;
                    const size_t gb0 = (((size_t)(n*64 + co)) << 16) + (size_t)h_r*256 + w0;
                    const size_t gb1 = gb0 + HW;   // co+1
                    #pragma unroll
                    for (int mi = 0; mi < 4; mi++) {
                        const float* cf = &c[mi*16 + nj*4];
                        const int px0 = Mq*64 + mi*16 + pxq;
                        g_convh[gb0 + px0]     = __float2half_rn(cf[0]);
                        g_convh[gb1 + px0]     = __float2half_rn(cf[1]);
                        g_convh[gb0 + px0 + 8] = __float2half_rn(cf[2]);
                        g_convh[gb1 + px0 + 8] = __float2half_rn(cf[3]);
                        accS2[nj].x += cf[0] + cf[2];
                        accS2[nj].y += cf[1] + cf[3];
                        accQ2[nj].x += cf[0]*cf[0] + cf[2]*cf[2];
                        accQ2[nj].y += cf[1]*cf[1] + cf[3]*cf[3];
                    }
                }
            }
            __syncthreads();   // all ldsm reads done before next stores
        }
    }

    // ---- stats: butterfly over lanes sharing (L&3), write own 32-co half ----
    #pragma unroll
    for (int nj = 0; nj < 4; nj++) {
        #pragma unroll
        for (int off = 4; off < 32; off <<= 1) {
            accS2[nj].x += __shfl_xor_sync(0xffffffffu, accS2[nj].x, off);
            accS2[nj].y += __shfl_xor_sync(0xffffffffu, accS2[nj].y, off);
            accQ2[nj].x += __shfl_xor_sync(0xffffffffu, accQ2[nj].x, off);
            accQ2[nj].y += __shfl_xor_sync(0xffffffffu, accQ2[nj].y, off);
        }
    }
    if (L < 4) {
        #pragma unroll
        for (int nj = 0; nj < 4; nj++) {
            const int lc = nj*8 + 2*L;
            sredS[wi*32 + lc]     = accS2[nj].x;
            sredS[wi*32 + lc + 1] = accS2[nj].y;
            sredQ[wi*32 + lc]     = accQ2[nj].x;
            sredQ[wi*32 + lc + 1] = accQ2[nj].y;
        }
    }
    __syncthreads();
    if (t < 64) {
        const int half = t >> 5;           // co<32 -> warps with (wi&1)==0
        const int lc = t & 31;
        float s = 0.f, q = 0.f;
        #pragma unroll
        for (int j = 0; j < 6; j++) {
            const int w = 2*j + half;
            s += sredS[w*32 + lc];
            q += sredQ[w*32 + lc];
        }
        g_psum[t*148 + blockIdx.x] = s;
        g_psq [t*148 + blockIdx.x] = q;
    }
}

// ---------------------------------------------------------------------------
__global__ void finalize_stats(const float* __restrict__ gamma,
                               const float* __restrict__ beta)
{
    int c = threadIdx.x;   // 64 threads
    float s = 0.f, q = 0.f;
    for (int b = 0; b < 148; b++) { s += g_psum[c*148 + b]; q += g_psq[c*148 + b]; }
    const float invM = 1.f / (float)M_PER_CH;
    float m   = s * invM;
    float var = q * invM - m*m;
    float inv = rsqrtf(var + 1e-5f);
    float sc  = gamma[c] * inv;
    g_scale[c] = sc;
    g_shift[c] = beta[c] - sc * m;
}

// ---------------------------------------------------------------------------
// normalize + ReLU + 4x4 block bitonic sort; write [a | y]  (DRAM roofline)
// ---------------------------------------------------------------------------
__global__ __launch_bounds__(256) void bn_sort_kernel(float* __restrict__ out)
{
    int tid = blockIdx.x * 256 + threadIdx.x;
    int bw = tid & 63, bh = (tid >> 6) & 63, c = (tid >> 12) & 63, n = tid >> 18;
    float sc = g_scale[c], sh = g_shift[c];

    size_t ibase = ((((size_t)(n*64 + c)) << 8) + bh*4) * 256 + bw*4;
    float v[16];
    #pragma unroll
    for (int r = 0; r < 4; r++) {
        uint2 raw = *(const uint2*)&g_convh[ibase + (size_t)r*256];
        float2 f01 = __half22float2(*(__half2*)&raw.x);
        float2 f23 = __half22float2(*(__half2*)&raw.y);
        v[r*4+0] = fmaxf(fmaf(f01.x, sc, sh), 0.f);
        v[r*4+1] = fmaxf(fmaf(f01.y, sc, sh), 0.f);
        v[r*4+2] = fmaxf(fmaf(f23.x, sc, sh), 0.f);
        v[r*4+3] = fmaxf(fmaf(f23.y, sc, sh), 0.f);
    }
    size_t obase = ((((size_t)(n*128 + c)) << 8) + bh*4) * 256 + bw*4;
    #pragma unroll
    for (int r = 0; r < 4; r++)
        *(float4*)&out[obase + (size_t)r*256] =
            make_float4(v[r*4+0], v[r*4+1], v[r*4+2], v[r*4+3]);

    #pragma unroll
    for (int k = 2; k <= 16; k <<= 1)
        #pragma unroll
        for (int j = k >> 1; j > 0; j >>= 1)
            #pragma unroll
            for (int i = 0; i < 16; i++) {
                int ix = i ^ j;
                if (ix > i) {
                    float a = v[i], b = v[ix];
                    float lo = fminf(a, b), hi = fmaxf(a, b);
                    bool up = ((i & k) == 0);
                    v[i] = up ? lo : hi; v[ix] = up ? hi : lo;
                }
            }

    size_t ybase = obase + ((size_t)64 << 16);
    #pragma unroll
    for (int r = 0; r < 4; r++)
        *(float4*)&out[ybase + (size_t)r*256] =
            make_float4(v[r*4+0], v[r*4+1], v[r*4+2], v[r*4+3]);
}

// ---------------------------------------------------------------------------
extern "C" void kernel_launch(void* const* d_in, const int* in_sizes, int n_in,
                              void* d_out, int out_size)
{
    const float* x     = (const float*)d_in[0];
    const float* wgt   = (const float*)d_in[1];
    // d_in[2] = conv_b : cancels exactly in training-mode BN
    const float* gamma = (const float*)d_in[3];
    const float* beta  = (const float*)d_in[4];
    float* out = (float*)d_out;

    cudaFuncSetAttribute(conv_tc, cudaFuncAttributeMaxDynamicSharedMemorySize, SMEM_REQ);
    conv_tc<<<148, 384, SMEM_REQ>>>(x, wgt);
    finalize_stats<<<1, 64>>>(gamma, beta);
    bn_sort_kernel<<<16384, 256>>>(out);
}